// round 1
// baseline (speedup 1.0000x reference)
#include <cuda_runtime.h>
#include <cstdint>

#define VNUM    100000
#define KNZ     8
#define BASE    64
#define DIM     9
#define BATCH   16
#define TV      128          // vertices per block
#define THREADS 256
#define SLAB    (BASE * DIM) // 576 floats per batch slab

// Flag: 1 if vb_index is int64 on device, 0 if int32. Set by detect_kernel each launch.
__device__ int g_vb_is64;

// Interpreting the vb buffer as int32 pairs: if the true dtype is int64 (values in
// [0,64), non-negative), every odd int32 slot is the zero high-word. If the true
// dtype is int32, odd slots are random values in [0,64) (zero w.p. 1/64 each).
// 4096 samples => misdetection probability ~(1/64)^4096 = 0.
__global__ void detect_vb_dtype_kernel(const int* __restrict__ vb32) {
    __shared__ int any_nonzero;
    if (threadIdx.x == 0) any_nonzero = 0;
    __syncthreads();
    for (int i = threadIdx.x; i < 4096; i += blockDim.x) {
        if (vb32[2 * i + 1] != 0) any_nonzero = 1;
    }
    __syncthreads();
    if (threadIdx.x == 0) g_vb_is64 = (any_nonzero ? 0 : 1);
}

__global__ __launch_bounds__(THREADS)
void skin_kernel(const float* __restrict__ base_fs,
                 const float* __restrict__ ws,
                 const void*  __restrict__ vb_raw,
                 float* __restrict__ out) {
    __shared__ float fs_s[BATCH * SLAB];  // 36864 B
    __shared__ float w_s[TV * KNZ];       //  4096 B
    __shared__ int   off_s[TV * KNZ];     //  4096 B

    const int tid = threadIdx.x;
    const int v0  = blockIdx.x * TV;

    // ---- Phase 1a: stage base_fs into smem (coalesced, L2-resident) ----
    for (int i = tid; i < BATCH * SLAB; i += THREADS)
        fs_s[i] = base_fs[i];

    // ---- Phase 1b: per-vertex softmax weights + gather offsets ----
    const int is64 = g_vb_is64;
    for (int t = tid; t < TV; t += THREADS) {
        const int v = v0 + t;
        if (v < VNUM) {
            // 8 contiguous weights, 32B aligned -> 2x float4
            const float4* wp = reinterpret_cast<const float4*>(ws + (size_t)v * KNZ);
            float4 a = wp[0], b4 = wp[1];
            float x[8] = {a.x, a.y, a.z, a.w, b4.x, b4.y, b4.z, b4.w};
            float m = x[0];
            #pragma unroll
            for (int j = 1; j < 8; j++) m = fmaxf(m, x[j]);
            float s = 0.f;
            #pragma unroll
            for (int j = 0; j < 8; j++) { x[j] = __expf(x[j] - m); s += x[j]; }
            const float inv = 1.f / s;

            int idx[8];
            if (is64) {
                const longlong2* ip =
                    reinterpret_cast<const longlong2*>((const char*)vb_raw + (size_t)v * KNZ * 8);
                #pragma unroll
                for (int j = 0; j < 4; j++) {
                    longlong2 ii = ip[j];
                    idx[2 * j]     = (int)ii.x;
                    idx[2 * j + 1] = (int)ii.y;
                }
            } else {
                const int4* ip =
                    reinterpret_cast<const int4*>((const char*)vb_raw + (size_t)v * KNZ * 4);
                int4 i0 = ip[0], i1 = ip[1];
                idx[0] = i0.x; idx[1] = i0.y; idx[2] = i0.z; idx[3] = i0.w;
                idx[4] = i1.x; idx[5] = i1.y; idx[6] = i1.z; idx[7] = i1.w;
            }
            #pragma unroll
            for (int j = 0; j < 8; j++) {
                w_s[t * KNZ + j]   = x[j] * inv;
                off_s[t * KNZ + j] = idx[j] * DIM;
            }
        }
    }
    __syncthreads();

    // ---- Phase 2: each thread owns one (vertex, dim) element across all batches ----
    // Per element: hoist 8 weights + 8 offsets into registers, then 16 batches of
    // (8 LDS + 8 FMA + 1 coalesced STG).
    const int nelem = TV * DIM;  // 1152
    for (int e = tid; e < nelem; e += THREADS) {
        const int tl = e / DIM;
        const int d  = e - tl * DIM;
        const int v  = v0 + tl;
        if (v < VNUM) {
            float w[8];
            int   p[8];
            #pragma unroll
            for (int j = 0; j < 8; j++) {
                w[j] = w_s[tl * KNZ + j];
                p[j] = off_s[tl * KNZ + j] + d;
            }
            const size_t obase = (size_t)v * DIM + d;
            #pragma unroll
            for (int b = 0; b < BATCH; b++) {
                const float* f = fs_s + b * SLAB;
                float acc = 0.f;
                #pragma unroll
                for (int j = 0; j < 8; j++) acc += w[j] * f[p[j]];
                out[(size_t)b * ((size_t)VNUM * DIM) + obase] = acc;
            }
        }
    }
}

extern "C" void kernel_launch(void* const* d_in, const int* in_sizes, int n_in,
                              void* d_out, int out_size) {
    const float* base_fs = (const float*)d_in[0];   // [16, 576] f32
    const float* ws      = (const float*)d_in[1];   // [800000] f32
    const void*  vb      = d_in[2];                 // [800000] i64 or i32 (detected)
    // d_in[3] = vv_index: statically known to be repeat(arange(VNUM), 8); unused.
    float* out = (float*)d_out;                     // [16, 100000, 9] f32

    detect_vb_dtype_kernel<<<1, 256>>>((const int*)vb);
    const int blocks = (VNUM + TV - 1) / TV;        // 782
    skin_kernel<<<blocks, THREADS>>>(base_fs, ws, vb, out);
}

// round 2
// speedup vs baseline: 1.2376x; 1.2376x over previous
#include <cuda_runtime.h>
#include <cstdint>

#define VNUM    100000
#define KNZ     8
#define BASE    64
#define DIM     9
#define BATCH   16
#define TV      128          // vertices per block
#define THREADS 256
#define SLAB    (BASE * DIM) // 576 rows
#define RSTRIDE 20           // padded batch stride (floats): 80B -> hits all 8 bank-quads

// fs_t: SLAB*RSTRIDE floats = 46080 B ; w_s: TV*8 = 4096 B ; off_s: TV*8 = 4096 B
#define SMEM_FS_FLOATS (SLAB * RSTRIDE)
#define SMEM_TOTAL_B   ((SMEM_FS_FLOATS + TV * KNZ) * 4 + TV * KNZ * 4)

// Flag: 1 if vb_index is int64 on device, 0 if int32. Set by detect kernel each launch.
__device__ int g_vb_is64;

// Interpreting vb as int32 pairs: if true dtype is int64 (values in [0,64)), every
// odd int32 slot is a zero high-word. If int32, odd slots are random in [0,64).
__global__ void detect_vb_dtype_kernel(const int* __restrict__ vb32) {
    __shared__ int any_nonzero;
    if (threadIdx.x == 0) any_nonzero = 0;
    __syncthreads();
    for (int i = threadIdx.x; i < 4096; i += blockDim.x)
        if (vb32[2 * i + 1] != 0) any_nonzero = 1;
    __syncthreads();
    if (threadIdx.x == 0) g_vb_is64 = (any_nonzero ? 0 : 1);
}

__global__ __launch_bounds__(THREADS)
void skin_kernel(const float* __restrict__ base_fs,
                 const float* __restrict__ ws,
                 const void*  __restrict__ vb_raw,
                 float* __restrict__ out) {
    extern __shared__ float smem[];
    float* fs_s  = smem;                              // [576][20] batch-major, padded
    float* w_s   = smem + SMEM_FS_FLOATS;             // [TV][8]
    int*   off_s = (int*)(smem + SMEM_FS_FLOATS + TV * KNZ); // [TV][8] = idx*9*RSTRIDE

    const int tid = threadIdx.x;
    const int v0  = blockIdx.x * TV;

    // ---- Phase 1a: stage base_fs transposed: fs_s[r*20 + b] = base_fs[b*576 + r] ----
    for (int i = tid; i < BATCH * SLAB; i += THREADS) {
        const int b = i / SLAB;
        const int r = i - b * SLAB;
        fs_s[r * RSTRIDE + b] = base_fs[i];
    }

    // ---- Phase 1b: per-vertex softmax weights + gather row offsets ----
    const int is64 = g_vb_is64;
    for (int t = tid; t < TV; t += THREADS) {
        const int v = v0 + t;
        if (v < VNUM) {
            const float4* wp = reinterpret_cast<const float4*>(ws + (size_t)v * KNZ);
            float4 a = wp[0], b4 = wp[1];
            float x[8] = {a.x, a.y, a.z, a.w, b4.x, b4.y, b4.z, b4.w};
            float m = x[0];
            #pragma unroll
            for (int j = 1; j < 8; j++) m = fmaxf(m, x[j]);
            float s = 0.f;
            #pragma unroll
            for (int j = 0; j < 8; j++) { x[j] = __expf(x[j] - m); s += x[j]; }
            const float inv = 1.f / s;

            int idx[8];
            if (is64) {
                const longlong2* ip =
                    reinterpret_cast<const longlong2*>((const char*)vb_raw + (size_t)v * KNZ * 8);
                #pragma unroll
                for (int j = 0; j < 4; j++) {
                    longlong2 ii = ip[j];
                    idx[2 * j]     = (int)ii.x;
                    idx[2 * j + 1] = (int)ii.y;
                }
            } else {
                const int4* ip =
                    reinterpret_cast<const int4*>((const char*)vb_raw + (size_t)v * KNZ * 4);
                int4 i0 = ip[0], i1 = ip[1];
                idx[0] = i0.x; idx[1] = i0.y; idx[2] = i0.z; idx[3] = i0.w;
                idx[4] = i1.x; idx[5] = i1.y; idx[6] = i1.z; idx[7] = i1.w;
            }
            #pragma unroll
            for (int j = 0; j < 8; j++) {
                w_s[t * KNZ + j]   = x[j] * inv;
                off_s[t * KNZ + j] = idx[j] * (DIM * RSTRIDE); // row base in floats
            }
        }
    }
    __syncthreads();

    // ---- Phase 2: thread owns (vertex, dim); all 16 batches via 4x LDS.128/base ----
    const int nelem = TV * DIM;  // 1152
    for (int e = tid; e < nelem; e += THREADS) {
        const int tl = e / DIM;
        const int d  = e - tl * DIM;
        const int v  = v0 + tl;
        if (v < VNUM) {
            float w[8];
            int   p[8];
            const int drow = d * RSTRIDE;
            #pragma unroll
            for (int j = 0; j < 8; j++) {
                w[j] = w_s[tl * KNZ + j];
                p[j] = off_s[tl * KNZ + j] + drow;
            }
            float acc[BATCH];
            #pragma unroll
            for (int b = 0; b < BATCH; b++) acc[b] = 0.f;

            #pragma unroll
            for (int j = 0; j < 8; j++) {
                const float4* f = reinterpret_cast<const float4*>(fs_s + p[j]);
                const float wj = w[j];
                float4 q0 = f[0], q1 = f[1], q2 = f[2], q3 = f[3];
                acc[0]  += wj * q0.x; acc[1]  += wj * q0.y;
                acc[2]  += wj * q0.z; acc[3]  += wj * q0.w;
                acc[4]  += wj * q1.x; acc[5]  += wj * q1.y;
                acc[6]  += wj * q1.z; acc[7]  += wj * q1.w;
                acc[8]  += wj * q2.x; acc[9]  += wj * q2.y;
                acc[10] += wj * q2.z; acc[11] += wj * q2.w;
                acc[12] += wj * q3.x; acc[13] += wj * q3.y;
                acc[14] += wj * q3.z; acc[15] += wj * q3.w;
            }

            const size_t obase = (size_t)v * DIM + d;
            #pragma unroll
            for (int b = 0; b < BATCH; b++)
                out[(size_t)b * ((size_t)VNUM * DIM) + obase] = acc[b];
        }
    }
}

extern "C" void kernel_launch(void* const* d_in, const int* in_sizes, int n_in,
                              void* d_out, int out_size) {
    const float* base_fs = (const float*)d_in[0];   // [16, 576] f32
    const float* ws      = (const float*)d_in[1];   // [800000] f32
    const void*  vb      = d_in[2];                 // [800000] i64 or i32 (detected)
    // d_in[3] = vv_index: statically repeat(arange(VNUM), 8); unused.
    float* out = (float*)d_out;                     // [16, 100000, 9] f32

    static bool attr_set = false;
    if (!attr_set) {
        cudaFuncSetAttribute(skin_kernel,
                             cudaFuncAttributeMaxDynamicSharedMemorySize, SMEM_TOTAL_B);
        attr_set = true;
    }

    detect_vb_dtype_kernel<<<1, 256>>>((const int*)vb);
    const int blocks = (VNUM + TV - 1) / TV;        // 782
    skin_kernel<<<blocks, THREADS, SMEM_TOTAL_B>>>(base_fs, ws, vb, out);
}